// round 14
// baseline (speedup 1.0000x reference)
#include <cuda_runtime.h>
#include <cuda_fp16.h>
#include <math.h>

// Problem constants
#define BB 4
#define TT 4096
#define CC 1024
#define HS 128
#define MM (BB * TT)

// ----------------------------------------------------------------------------
// Scratch (device globals). fp16 q/k/v. q pre-scaled by log2(e)/sqrt(HS).
// ----------------------------------------------------------------------------
__device__ __half g_q[MM * HS];
__device__ __half g_k[MM * HS];
__device__ __half g_v[MM * HS];

// ----------------------------------------------------------------------------
// helpers
// ----------------------------------------------------------------------------
__device__ __forceinline__ void mma16(float c[4],
                                      unsigned a0, unsigned a1, unsigned a2, unsigned a3,
                                      unsigned b0, unsigned b1) {
    asm volatile(
        "mma.sync.aligned.m16n8k16.row.col.f32.f16.f16.f32 "
        "{%0,%1,%2,%3},{%4,%5,%6,%7},{%8,%9},{%0,%1,%2,%3};"
        : "+f"(c[0]), "+f"(c[1]), "+f"(c[2]), "+f"(c[3])
        : "r"(a0), "r"(a1), "r"(a2), "r"(a3), "r"(b0), "r"(b1));
}
__device__ __forceinline__ void ldsm4(unsigned &r0, unsigned &r1, unsigned &r2, unsigned &r3,
                                      const __half* p) {
    unsigned a = (unsigned)__cvta_generic_to_shared(p);
    asm volatile("ldmatrix.sync.aligned.m8n8.x4.shared.b16 {%0,%1,%2,%3}, [%4];"
                 : "=r"(r0), "=r"(r1), "=r"(r2), "=r"(r3) : "r"(a));
}
__device__ __forceinline__ void ldsm4t(unsigned &r0, unsigned &r1, unsigned &r2, unsigned &r3,
                                       const __half* p) {
    unsigned a = (unsigned)__cvta_generic_to_shared(p);
    asm volatile("ldmatrix.sync.aligned.m8n8.x4.trans.shared.b16 {%0,%1,%2,%3}, [%4];"
                 : "=r"(r0), "=r"(r1), "=r"(r2), "=r"(r3) : "r"(a));
}
__device__ __forceinline__ unsigned ph2(float a, float b) {
    __half2 h = __floats2half2_rn(a, b);
    return *reinterpret_cast<unsigned*>(&h);
}
__device__ __forceinline__ float fexp2(float x) {
    float y; asm("ex2.approx.f32 %0, %1;" : "=f"(y) : "f"(x)); return y;
}
__device__ __forceinline__ void cpa16h(__half* smem_dst, const __half* gsrc) {
    unsigned s = (unsigned)__cvta_generic_to_shared(smem_dst);
    asm volatile("cp.async.cg.shared.global [%0], [%1], 16;" :: "r"(s), "l"(gsrc));
}
#define CP_COMMIT() asm volatile("cp.async.commit_group;")
#define CP_WAIT0()  asm volatile("cp.async.wait_group 0;")
#define PAIR_BAR(id) asm volatile("bar.sync %0, 64;" :: "r"((id) + 1) : "memory")

// Q pre-scale: (1/sqrt(128)) * log2(e)  -> softmax uses ex2 directly
#define Q_SCALE 0.1275310250309574f

// ----------------------------------------------------------------------------
// QKV projection, fp16 MMA + ldmatrix (R11, measured ~63.7us). Unchanged.
// ----------------------------------------------------------------------------
#define P_TK 32
#define XSTRH 72
#define WSTRH 136

__global__ __launch_bounds__(256, 2)
void proj_kernel(const float* __restrict__ x,
                 const float* __restrict__ Wq,
                 const float* __restrict__ Wk,
                 const float* __restrict__ Wv)
{
    __shared__ __half Xh[128 * XSTRH];
    __shared__ __half Wh[P_TK * WSTRH];

    const float* W   = (blockIdx.y == 0) ? Wq : (blockIdx.y == 1) ? Wk : Wv;
    __half*      out = (blockIdx.y == 0) ? g_q : (blockIdx.y == 1) ? g_k : g_v;
    const float  osc = (blockIdx.y == 0) ? Q_SCALE : 1.0f;

    const int row0 = blockIdx.x * 128;
    const int tid  = threadIdx.x, lane = tid & 31, w = tid >> 5;
    const int m0   = (w >> 1) * 32;
    const int half = w & 1;
    const int lg = lane >> 3, lr = lane & 7;

    float4 xr[4], wr[4];
    const int xrr[4] = { (tid) >> 3, (tid + 256) >> 3, (tid + 512) >> 3, (tid + 768) >> 3 };
    const int xcc    = (tid & 7) * 4;
    const int wrr[4] = { (tid) >> 5, (tid + 256) >> 5, (tid + 512) >> 5, (tid + 768) >> 5 };
    const int wcc    = (tid & 31) * 4;

    auto load_regs = [&](int kt) {
#pragma unroll
        for (int it = 0; it < 4; it++)
            xr[it] = *(const float4*)&x[(size_t)(row0 + xrr[it]) * CC + kt + xcc];
#pragma unroll
        for (int it = 0; it < 4; it++)
            wr[it] = *(const float4*)&W[(size_t)(kt + wrr[it]) * HS + wcc];
    };
    auto store_smem = [&]() {
#pragma unroll
        for (int it = 0; it < 4; it++) {
            float4 v = xr[it];
            *(uint2*)&Xh[xrr[it] * XSTRH + xcc] = make_uint2(ph2(v.x, v.y), ph2(v.z, v.w));
        }
#pragma unroll
        for (int it = 0; it < 4; it++) {
            float4 v = wr[it];
            *(uint2*)&Wh[wrr[it] * WSTRH + wcc] = make_uint2(ph2(v.x, v.y), ph2(v.z, v.w));
        }
    };

    float ac[2][8][4];
#pragma unroll
    for (int mf = 0; mf < 2; mf++)
#pragma unroll
        for (int f = 0; f < 8; f++)
#pragma unroll
            for (int r = 0; r < 4; r++) ac[mf][f][r] = 0.f;

    load_regs(0);
    for (int kt = 0; kt < CC; kt += P_TK) {
        store_smem();
        __syncthreads();
        if (kt + P_TK < CC) load_regs(kt + P_TK);

#pragma unroll
        for (int kg = 0; kg < 2; kg++) {
            unsigned a[2][4];
#pragma unroll
            for (int mf = 0; mf < 2; mf++)
                ldsm4(a[mf][0], a[mf][1], a[mf][2], a[mf][3],
                      &Xh[(m0 + mf * 16 + (lg & 1) * 8 + lr) * XSTRH + kg * 16 + (lg >> 1) * 8]);
#pragma unroll
            for (int np = 0; np < 4; np++) {
                unsigned b0, b1, b2, b3;
                ldsm4t(b0, b1, b2, b3,
                       &Wh[(kg * 16 + (lg & 1) * 8 + lr) * WSTRH + half * 64 + np * 16 + (lg >> 1) * 8]);
#pragma unroll
                for (int mf = 0; mf < 2; mf++) {
                    mma16(ac[mf][np * 2],     a[mf][0], a[mf][1], a[mf][2], a[mf][3], b0, b1);
                    mma16(ac[mf][np * 2 + 1], a[mf][0], a[mf][1], a[mf][2], a[mf][3], b2, b3);
                }
            }
        }
        __syncthreads();
    }

#pragma unroll
    for (int mf = 0; mf < 2; mf++) {
        int r = row0 + m0 + mf * 16 + (lane >> 2);
#pragma unroll
        for (int f = 0; f < 8; f++) {
            int c = half * 64 + f * 8 + 2 * (lane & 3);
            *(__half2*)&out[(size_t)r * HS + c] =
                __floats2half2_rn(ac[mf][f][0] * osc, ac[mf][f][1] * osc);
            *(__half2*)&out[(size_t)(r + 8) * HS + c] =
                __floats2half2_rn(ac[mf][f][2] * osc, ac[mf][f][3] * osc);
        }
    }
}

// ----------------------------------------------------------------------------
// Flash attention: BM=32, BN=64, 128 threads (4 warps), 2 CTAs/SM.
// Grid: 64 balanced pairs (qi, 127-qi) x 4 batches = 256 CTAs on 148 SMs.
// Warp = 16 rows x 32 s-cols (own half). Q frags register-resident;
// own-half P in regs, partner half via smem ldmatrix. 65 K-iters/CTA constant.
// ----------------------------------------------------------------------------
#define QSTRH 136
#define PSTRH 72

#define H_QS   0
#define H_KS   (H_QS + 32 * QSTRH)
#define H_VS   (H_KS + 2 * 64 * QSTRH)
#define H_PS   (H_VS + 2 * 64 * QSTRH)
#define H_TOT  (H_PS + 32 * PSTRH)
#define F_TOT  192
#define ATTN_SMEM_BYTES (H_TOT * 2 + F_TOT * 4)

__global__ __launch_bounds__(128, 2)
void attn_kernel(float* __restrict__ out)
{
    extern __shared__ char smraw[];
    __half* Qs  = (__half*)smraw;                 // 32 x QSTRH
    __half* Ksb = Qs + 32 * QSTRH;                // 2 x 64 x QSTRH
    __half* Vsb = Ksb + 2 * 64 * QSTRH;           // 2 x 64 x QSTRH
    __half* Ps  = Vsb + 2 * 64 * QSTRH;           // 32 x PSTRH
    float*  fst = (float*)(smraw + H_TOT * 2);
    float* pmax = fst;          // [64]  half*32 + row
    float* psum = fst + 64;     // [64]
    float* m_sh = fst + 128;    // [32]
    float* l_sh = fst + 160;    // [32]

    const int tid = threadIdx.x, lane = tid & 31, w = tid >> 5;
    const int rg = w >> 1;      // row group (16 rows) within BM=32
    const int half = w & 1;     // s-col half
    const int b = blockIdx.y;

    const __half* qb = g_q + (size_t)b * TT * HS;
    const __half* kb = g_k + (size_t)b * TT * HS;
    const __half* vb = g_v + (size_t)b * TT * HS;

    const int r0l = rg * 16 + (lane >> 2);   // local row 0..31
    const int r1l = r0l + 8;
    const int lg = lane >> 3, lr = lane & 7;

    for (int phase = 0; phase < 2; phase++) {
        const int qi = phase ? (127 - (int)blockIdx.x) : (int)blockIdx.x;  // 32-row tile idx
        const int jmax = qi >> 1;                                          // BN=64 tiles
        __syncthreads();   // previous phase done with all smem

        // Prologue: async K/V (j=0) + Q
        {
            const __half* qg = qb + (size_t)qi * 32 * HS;
#pragma unroll
            for (int it = 0; it < 8; it++) {
                int ch = tid + it * 128;
                int r = ch >> 4, c = (ch & 15) * 8;
                cpa16h(&Ksb[r * QSTRH + c], &kb[(size_t)r * HS + c]);
                cpa16h(&Vsb[r * QSTRH + c], &vb[(size_t)r * HS + c]);
            }
#pragma unroll
            for (int it = 0; it < 4; it++) {
                int ch = tid + it * 128;
                int r = ch >> 4, c = (ch & 15) * 8;
                cpa16h(&Qs[r * QSTRH + c], &qg[(size_t)r * HS + c]);
            }
            CP_COMMIT();
        }
        if (tid < 32) { m_sh[tid] = -1e30f; l_sh[tid] = 0.f; }

        CP_WAIT0();
        __syncthreads();

        // Q fragments -> registers (whole phase). scale*log2e pre-folded.
        unsigned qa[8][4];
        {
            const __half* qbase = &Qs[(rg * 16 + (lg & 1) * 8 + lr) * QSTRH + (lg >> 1) * 8];
#pragma unroll
            for (int ks = 0; ks < 8; ks++)
                ldsm4(qa[ks][0], qa[ks][1], qa[ks][2], qa[ks][3], qbase + ks * 16);
        }

        float o[8][4];
#pragma unroll
        for (int f = 0; f < 8; f++) { o[f][0] = o[f][1] = o[f][2] = o[f][3] = 0.f; }

        const int gr0 = qi * 32 + r0l;   // global rows for causal mask
        const int gr1 = gr0 + 8;

        for (int j = 0; j <= jmax; j++) {
            const int cur = j & 1;
            __half* Ks = Ksb + cur * 64 * QSTRH;
            __half* Vs = Vsb + cur * 64 * QSTRH;

            if (j > 0) { CP_WAIT0(); }
            __syncthreads();

            if (j < jmax) {
                const __half* kg = kb + (size_t)(j + 1) * 64 * HS;
                const __half* vg = vb + (size_t)(j + 1) * 64 * HS;
                __half* Kn = Ksb + (1 - cur) * 64 * QSTRH;
                __half* Vn = Vsb + (1 - cur) * 64 * QSTRH;
#pragma unroll
                for (int it = 0; it < 8; it++) {
                    int ch = tid + it * 128;
                    int r = ch >> 4, c = (ch & 15) * 8;
                    cpa16h(&Kn[r * QSTRH + c], &kg[(size_t)r * HS + c]);
                    cpa16h(&Vn[r * QSTRH + c], &vg[(size_t)r * HS + c]);
                }
                CP_COMMIT();
            }

            // ---- S = Q K^T : 16 rows x 32 cols (own half), k=128 ----
            float s[4][4];
#pragma unroll
            for (int f = 0; f < 4; f++) { s[f][0] = s[f][1] = s[f][2] = s[f][3] = 0.f; }
            {
                const __half* kbase = &Ks[(half * 32 + (lg >> 1) * 8 + lr) * QSTRH + (lg & 1) * 8];
#pragma unroll
                for (int ks = 0; ks < 8; ks++) {
#pragma unroll
                    for (int fp = 0; fp < 2; fp++) {
                        unsigned kb0, kb1, kb2, kb3;
                        ldsm4(kb0, kb1, kb2, kb3, kbase + fp * 16 * QSTRH + ks * 16);
                        mma16(s[fp * 2],     qa[ks][0], qa[ks][1], qa[ks][2], qa[ks][3], kb0, kb1);
                        mma16(s[fp * 2 + 1], qa[ks][0], qa[ks][1], qa[ks][2], qa[ks][3], kb2, kb3);
                    }
                }
            }

            // Causal mask (last K-tile; global row/col compare)
            if (j == jmax) {
#pragma unroll
                for (int f = 0; f < 4; f++) {
                    int gc = j * 64 + half * 32 + f * 8 + 2 * (lane & 3);
                    if (gc     > gr0) s[f][0] = -1e30f;
                    if (gc + 1 > gr0) s[f][1] = -1e30f;
                    if (gc     > gr1) s[f][2] = -1e30f;
                    if (gc + 1 > gr1) s[f][3] = -1e30f;
                }
            }

            // Row max (per half)
            float rm0 = -1e30f, rm1 = -1e30f;
#pragma unroll
            for (int f = 0; f < 4; f++) {
                rm0 = fmaxf(rm0, fmaxf(s[f][0], s[f][1]));
                rm1 = fmaxf(rm1, fmaxf(s[f][2], s[f][3]));
            }
            rm0 = fmaxf(rm0, __shfl_xor_sync(0xffffffffu, rm0, 1));
            rm0 = fmaxf(rm0, __shfl_xor_sync(0xffffffffu, rm0, 2));
            rm1 = fmaxf(rm1, __shfl_xor_sync(0xffffffffu, rm1, 1));
            rm1 = fmaxf(rm1, __shfl_xor_sync(0xffffffffu, rm1, 2));
            if ((lane & 3) == 0) {
                pmax[half * 32 + r0l] = rm0;
                pmax[half * 32 + r1l] = rm1;
            }
            PAIR_BAR(rg);

            // Online softmax (ex2 domain); P -> fp16 regs + smem
            float mold0 = m_sh[r0l], mold1 = m_sh[r1l];
            float mn0 = fmaxf(mold0, fmaxf(pmax[r0l], pmax[32 + r0l]));
            float mn1 = fmaxf(mold1, fmaxf(pmax[r1l], pmax[32 + r1l]));
            float f0 = fexp2(mold0 - mn0), f1 = fexp2(mold1 - mn1);
            float sum0 = 0.f, sum1 = 0.f;
            unsigned own_a[2][4];
#pragma unroll
            for (int f = 0; f < 4; f++) {
                int c = half * 32 + f * 8 + 2 * (lane & 3);
                float p00 = fexp2(s[f][0] - mn0), p01 = fexp2(s[f][1] - mn0);
                float p10 = fexp2(s[f][2] - mn1), p11 = fexp2(s[f][3] - mn1);
                sum0 += p00 + p01; sum1 += p10 + p11;
                unsigned h2a = ph2(p00, p01);
                unsigned h2b = ph2(p10, p11);
                *(unsigned*)&Ps[r0l * PSTRH + c] = h2a;
                *(unsigned*)&Ps[r1l * PSTRH + c] = h2b;
                own_a[f >> 1][(f & 1) * 2]     = h2a;
                own_a[f >> 1][(f & 1) * 2 + 1] = h2b;
            }
            sum0 += __shfl_xor_sync(0xffffffffu, sum0, 1);
            sum0 += __shfl_xor_sync(0xffffffffu, sum0, 2);
            sum1 += __shfl_xor_sync(0xffffffffu, sum1, 1);
            sum1 += __shfl_xor_sync(0xffffffffu, sum1, 2);
            if ((lane & 3) == 0) {
                psum[half * 32 + r0l] = sum0;
                psum[half * 32 + r1l] = sum1;
            }

            // Rescale O
#pragma unroll
            for (int f = 0; f < 8; f++) {
                o[f][0] *= f0; o[f][1] *= f0; o[f][2] *= f1; o[f][3] *= f1;
            }
            PAIR_BAR(rg);

            // Stats update (pair-local)
            if (half == 0 && (lane & 3) == 0) {
#pragma unroll
                for (int rr = 0; rr < 2; rr++) {
                    int r = rr ? r1l : r0l;
                    float mo = m_sh[r];
                    float mn = fmaxf(mo, fmaxf(pmax[r], pmax[32 + r]));
                    l_sh[r] = l_sh[r] * fexp2(mo - mn) + psum[r] + psum[32 + r];
                    m_sh[r] = mn;
                }
            }

            // ---- O += P V : warp = 16 rows x 64 hs-half, k=64 s-cols ----
            {
                const __half* vbase = &Vs[((lg & 1) * 8 + lr) * QSTRH + half * 64 + (lg >> 1) * 8];
                const __half* pbase = &Ps[(rg * 16 + (lg & 1) * 8 + lr) * PSTRH + (lg >> 1) * 8];
#pragma unroll
                for (int gs = 0; gs < 4; gs++) {
                    unsigned a0, a1, a2, a3;
                    if ((gs >> 1) == half) {
                        int loc = gs & 1;
                        a0 = own_a[loc][0]; a1 = own_a[loc][1];
                        a2 = own_a[loc][2]; a3 = own_a[loc][3];
                    } else {
                        ldsm4(a0, a1, a2, a3, pbase + gs * 16);
                    }
#pragma unroll
                    for (int np = 0; np < 4; np++) {
                        unsigned vb0, vb1, vb2, vb3;
                        ldsm4t(vb0, vb1, vb2, vb3, vbase + gs * 16 * QSTRH + np * 16);
                        mma16(o[np * 2],     a0, a1, a2, a3, vb0, vb1);
                        mma16(o[np * 2 + 1], a0, a1, a2, a3, vb2, vb3);
                    }
                }
            }
        }

        // Normalize and store
        PAIR_BAR(rg);
        float li0 = 1.f / l_sh[r0l];
        float li1 = 1.f / l_sh[r1l];
        float* ob = out + ((size_t)b * TT + (size_t)qi * 32) * HS;
#pragma unroll
        for (int f = 0; f < 8; f++) {
            int c = half * 64 + f * 8 + 2 * (lane & 3);
            *(float2*)&ob[(size_t)r0l * HS + c] = make_float2(o[f][0] * li0, o[f][1] * li0);
            *(float2*)&ob[(size_t)r1l * HS + c] = make_float2(o[f][2] * li1, o[f][3] * li1);
        }
    }
}

// ----------------------------------------------------------------------------
// Launcher
// ----------------------------------------------------------------------------
extern "C" void kernel_launch(void* const* d_in, const int* in_sizes, int n_in,
                              void* d_out, int out_size)
{
    const float* x  = (const float*)d_in[0];
    const float* Wq = (const float*)d_in[1];
    const float* Wk = (const float*)d_in[2];
    const float* Wv = (const float*)d_in[3];
    float* out = (float*)d_out;

    dim3 pg(MM / 128, 3);
    proj_kernel<<<pg, 256>>>(x, Wq, Wk, Wv);

    cudaFuncSetAttribute(attn_kernel,
                         cudaFuncAttributeMaxDynamicSharedMemorySize,
                         ATTN_SMEM_BYTES);
    dim3 ag(64, BB);   // 64 balanced 32-row pairs x 4 batches = 256 CTAs
    attn_kernel<<<ag, 128, ATTN_SMEM_BYTES>>>(out);
}